// round 4
// baseline (speedup 1.0000x reference)
#include <cuda_runtime.h>
#include <cstdint>

#define DEV_INLINE __device__ __forceinline__

// ---------------------------------------------------------------------------
// Problem constants: B=4, T=2048, E=2048, H=16, KV=4, G=4, D=128
// ---------------------------------------------------------------------------

// Scratch (device-global: allocation-free per harness rules)
__device__ float g_Q [4 * 2048 * 2048];  // (B*T, H*D)   64 MB
__device__ float g_K [4 * 2048 * 512];   // (B*T, KV*D)  16 MB
__device__ float g_V [4 * 2048 * 512];   // (B*T, KV*D)  16 MB
__device__ float g_AY[4 * 2048 * 2048];  // (B*T, H*D)   64 MB

DEV_INLINE unsigned f2tf(float f) {
    unsigned u;
    asm("cvt.rna.tf32.f32 %0, %1;" : "=r"(u) : "f"(f));
    return u;
}
DEV_INLINE float tfr(float f) { return __uint_as_float(f2tf(f)); }

DEV_INLINE void mma8(float* c, const unsigned* a, const unsigned* b) {
    asm("mma.sync.aligned.m16n8k8.row.col.f32.tf32.tf32.f32 "
        "{%0,%1,%2,%3}, {%4,%5,%6,%7}, {%8,%9}, {%0,%1,%2,%3};"
        : "+f"(c[0]), "+f"(c[1]), "+f"(c[2]), "+f"(c[3])
        : "r"(a[0]), "r"(a[1]), "r"(a[2]), "r"(a[3]), "r"(b[0]), "r"(b[1]));
}

// ---------------------------------------------------------------------------
// tf32 GEMM: C(MxN) = A(MxK) @ B(KxN), all row-major. M from grid (128/CTA).
// BM=128 BN=128 BK=16; 256 threads = 8 warps in 2(m) x 4(n); warp tile 64x32.
// smem strides 20 / 136 chosen so fragment LDS are bank-conflict-free.
// ---------------------------------------------------------------------------
template <int N, int K>
__global__ __launch_bounds__(256) void gemm_tf32(const float* __restrict__ A,
                                                 const float* __restrict__ B,
                                                 float* __restrict__ C) {
    __shared__ float As[128][20];
    __shared__ float Bs[16][136];

    const int tid  = threadIdx.x;
    const int lane = tid & 31, wid = tid >> 5;
    const int g = lane >> 2, t = lane & 3;
    const int wm = wid & 1, wn = wid >> 1;
    const int bm = blockIdx.y * 128, bn = blockIdx.x * 128;

    float acc[4][4][4];
#pragma unroll
    for (int mi = 0; mi < 4; mi++)
#pragma unroll
        for (int ni = 0; ni < 4; ni++)
#pragma unroll
            for (int j = 0; j < 4; j++) acc[mi][ni][j] = 0.f;

    for (int k0 = 0; k0 < K; k0 += 16) {
        // A tile 128x16
#pragma unroll
        for (int i = 0; i < 2; i++) {
            int idx = tid * 2 + i;
            int r = idx >> 2, c4 = (idx & 3) << 2;
            float4 v = *(const float4*)(A + (size_t)(bm + r) * K + (k0 + c4));
            float4 w;
            w.x = tfr(v.x); w.y = tfr(v.y); w.z = tfr(v.z); w.w = tfr(v.w);
            *(float4*)&As[r][c4] = w;
        }
        // B tile 16x128
#pragma unroll
        for (int i = 0; i < 2; i++) {
            int idx = tid * 2 + i;
            int r = idx >> 5, c4 = (idx & 31) << 2;
            float4 v = *(const float4*)(B + (size_t)(k0 + r) * N + (bn + c4));
            float4 w;
            w.x = tfr(v.x); w.y = tfr(v.y); w.z = tfr(v.z); w.w = tfr(v.w);
            *(float4*)&Bs[r][c4] = w;
        }
        __syncthreads();

#pragma unroll
        for (int ks = 0; ks < 2; ks++) {
            const int kc = ks * 8;
            unsigned aF[4][4], bF[4][2];
#pragma unroll
            for (int mi = 0; mi < 4; mi++) {
                int r = wm * 64 + mi * 16;
                aF[mi][0] = __float_as_uint(As[r + g][kc + t]);
                aF[mi][1] = __float_as_uint(As[r + g + 8][kc + t]);
                aF[mi][2] = __float_as_uint(As[r + g][kc + t + 4]);
                aF[mi][3] = __float_as_uint(As[r + g + 8][kc + t + 4]);
            }
#pragma unroll
            for (int ni = 0; ni < 4; ni++) {
                int cN = wn * 32 + ni * 8 + g;
                bF[ni][0] = __float_as_uint(Bs[kc + t][cN]);
                bF[ni][1] = __float_as_uint(Bs[kc + t + 4][cN]);
            }
#pragma unroll
            for (int mi = 0; mi < 4; mi++)
#pragma unroll
                for (int ni = 0; ni < 4; ni++) mma8(acc[mi][ni], aF[mi], bF[ni]);
        }
        __syncthreads();
    }

#pragma unroll
    for (int mi = 0; mi < 4; mi++) {
        int r0 = bm + wm * 64 + mi * 16 + g;
#pragma unroll
        for (int ni = 0; ni < 4; ni++) {
            int cN = bn + wn * 32 + ni * 8 + 2 * t;
            *(float2*)(C + (size_t)r0 * N + cN) =
                make_float2(acc[mi][ni][0], acc[mi][ni][1]);
            *(float2*)(C + (size_t)(r0 + 8) * N + cN) =
                make_float2(acc[mi][ni][2], acc[mi][ni][3]);
        }
    }
}

// ---------------------------------------------------------------------------
// Flash attention (causal, GQA). Grid (T/64, H, B), 128 threads = 4 warps.
// Warp w owns 16 query rows. Key tiles of 32. tf32 mma for QK^T and PV.
// P re-fragmented via padded per-warp smem tile (C-layout != A-layout).
// ---------------------------------------------------------------------------
struct AttnSmem {
    float Qs[64][132];      // stride 132: frag loads conflict-free
    float Ks[32][132];
    float Vs[32][136];      // stride 136: B-frag loads conflict-free
    float Ps[4][16][36];    // per-warp P tile, stride 36
};

__global__ __launch_bounds__(128) void attn_flash(const float* __restrict__ Q,
                                                  const float* __restrict__ Kg,
                                                  const float* __restrict__ Vg,
                                                  float* __restrict__ Y) {
    extern __shared__ char smem_raw[];
    AttnSmem& S = *reinterpret_cast<AttnSmem*>(smem_raw);

    const int b = blockIdx.z, h = blockIdx.y, qb = blockIdx.x;
    const int kv = h >> 2;  // G = 4
    const int tid = threadIdx.x, w = tid >> 5, lane = tid & 31;
    const int g = lane >> 2, t = lane & 3;
    const float scale = 0.08838834764831845f;  // 1/sqrt(128)

    const float* Qb = Q + ((size_t)(b * 2048 + qb * 64)) * 2048 + h * 128;
    const float* Kb = Kg + ((size_t)b * 2048) * 512 + kv * 128;
    const float* Vb = Vg + ((size_t)b * 2048) * 512 + kv * 128;
    float* Yb = Y + ((size_t)(b * 2048 + qb * 64)) * 2048 + h * 128;

    // Stage Q block (64x128) into smem, tf32-rounded
#pragma unroll
    for (int i = 0; i < 16; i++) {
        int idx = i * 128 + tid;
        int r = idx >> 5, c4 = (idx & 31) << 2;
        float4 v = *(const float4*)(Qb + (size_t)r * 2048 + c4);
        float4 wv;
        wv.x = tfr(v.x); wv.y = tfr(v.y); wv.z = tfr(v.z); wv.w = tfr(v.w);
        *(float4*)&S.Qs[r][c4] = wv;
    }
    __syncthreads();

    // Q fragments live in registers for the whole CTA (16 k-steps x 4 regs)
    unsigned qF[16][4];
#pragma unroll
    for (int ks = 0; ks < 16; ks++) {
        int kc = ks * 8;
        int r = w * 16;
        qF[ks][0] = __float_as_uint(S.Qs[r + g][kc + t]);
        qF[ks][1] = __float_as_uint(S.Qs[r + g + 8][kc + t]);
        qF[ks][2] = __float_as_uint(S.Qs[r + g][kc + t + 4]);
        qF[ks][3] = __float_as_uint(S.Qs[r + g + 8][kc + t + 4]);
    }

    float O[16][4];
#pragma unroll
    for (int i = 0; i < 16; i++)
#pragma unroll
        for (int j = 0; j < 4; j++) O[i][j] = 0.f;
    float m0 = -1e30f, m1 = -1e30f, l0 = 0.f, l1 = 0.f;

    const int qr0 = qb * 64 + w * 16 + g;
    const int qr1 = qr0 + 8;
    const int qmaxw = qb * 64 + w * 16 + 15;
    const int ntiles = qb * 2 + 2;  // keys 0 .. qb*64+63

    for (int jt = 0; jt < ntiles; jt++) {
        const int jbase = jt * 32;
        __syncthreads();  // previous tile fully consumed
        // cooperative K/V tile load (32x128 each)
#pragma unroll
        for (int i = 0; i < 8; i++) {
            int idx = i * 128 + tid;
            int r = idx >> 5, c4 = (idx & 31) << 2;
            float4 kv4 = *(const float4*)(Kb + (size_t)(jbase + r) * 512 + c4);
            float4 w1;
            w1.x = tfr(kv4.x); w1.y = tfr(kv4.y); w1.z = tfr(kv4.z); w1.w = tfr(kv4.w);
            *(float4*)&S.Ks[r][c4] = w1;
            float4 vv4 = *(const float4*)(Vb + (size_t)(jbase + r) * 512 + c4);
            float4 w2;
            w2.x = tfr(vv4.x); w2.y = tfr(vv4.y); w2.z = tfr(vv4.z); w2.w = tfr(vv4.w);
            *(float4*)&S.Vs[r][c4] = w2;
        }
        __syncthreads();

        if (jbase > qmaxw) continue;  // tile fully masked for this warp

        // S = Q @ K^T  (16 x 32)
        float s[4][4];
#pragma unroll
        for (int ni = 0; ni < 4; ni++)
#pragma unroll
            for (int j = 0; j < 4; j++) s[ni][j] = 0.f;
#pragma unroll
        for (int ks = 0; ks < 16; ks++) {
#pragma unroll
            for (int ni = 0; ni < 4; ni++) {
                unsigned bK[2];
                bK[0] = __float_as_uint(S.Ks[ni * 8 + g][ks * 8 + t]);
                bK[1] = __float_as_uint(S.Ks[ni * 8 + g][ks * 8 + t + 4]);
                mma8(s[ni], qF[ks], bK);
            }
        }

        // scale + causal mask
#pragma unroll
        for (int ni = 0; ni < 4; ni++) {
            int col = jbase + ni * 8 + 2 * t;
            s[ni][0] = (col     <= qr0) ? s[ni][0] * scale : -1e30f;
            s[ni][1] = (col + 1 <= qr0) ? s[ni][1] * scale : -1e30f;
            s[ni][2] = (col     <= qr1) ? s[ni][2] * scale : -1e30f;
            s[ni][3] = (col + 1 <= qr1) ? s[ni][3] * scale : -1e30f;
        }

        // online softmax row statistics
        float tm0 = -1e30f, tm1 = -1e30f;
#pragma unroll
        for (int ni = 0; ni < 4; ni++) {
            tm0 = fmaxf(tm0, fmaxf(s[ni][0], s[ni][1]));
            tm1 = fmaxf(tm1, fmaxf(s[ni][2], s[ni][3]));
        }
        tm0 = fmaxf(tm0, __shfl_xor_sync(0xffffffffu, tm0, 1));
        tm0 = fmaxf(tm0, __shfl_xor_sync(0xffffffffu, tm0, 2));
        tm1 = fmaxf(tm1, __shfl_xor_sync(0xffffffffu, tm1, 1));
        tm1 = fmaxf(tm1, __shfl_xor_sync(0xffffffffu, tm1, 2));
        float nm0 = fmaxf(m0, tm0), nm1 = fmaxf(m1, tm1);
        float corr0 = __expf(m0 - nm0), corr1 = __expf(m1 - nm1);

        float ls0 = 0.f, ls1 = 0.f;
#pragma unroll
        for (int ni = 0; ni < 4; ni++) {
            s[ni][0] = __expf(s[ni][0] - nm0);
            s[ni][1] = __expf(s[ni][1] - nm0);
            s[ni][2] = __expf(s[ni][2] - nm1);
            s[ni][3] = __expf(s[ni][3] - nm1);
            ls0 += s[ni][0] + s[ni][1];
            ls1 += s[ni][2] + s[ni][3];
        }
        ls0 += __shfl_xor_sync(0xffffffffu, ls0, 1);
        ls0 += __shfl_xor_sync(0xffffffffu, ls0, 2);
        ls1 += __shfl_xor_sync(0xffffffffu, ls1, 1);
        ls1 += __shfl_xor_sync(0xffffffffu, ls1, 2);
        l0 = l0 * corr0 + ls0;
        l1 = l1 * corr1 + ls1;
        m0 = nm0;
        m1 = nm1;

        // rescale O accumulator
#pragma unroll
        for (int nf = 0; nf < 16; nf++) {
            O[nf][0] *= corr0; O[nf][1] *= corr0;
            O[nf][2] *= corr1; O[nf][3] *= corr1;
        }

        // P (C-layout) -> per-warp smem -> A-layout fragments
#pragma unroll
        for (int ni = 0; ni < 4; ni++) {
            *(float2*)&S.Ps[w][g][ni * 8 + 2 * t] =
                make_float2(__uint_as_float(f2tf(s[ni][0])),
                            __uint_as_float(f2tf(s[ni][1])));
            *(float2*)&S.Ps[w][g + 8][ni * 8 + 2 * t] =
                make_float2(__uint_as_float(f2tf(s[ni][2])),
                            __uint_as_float(f2tf(s[ni][3])));
        }
        __syncwarp();

        // O += P @ V   (16x32 @ 32x128)
#pragma unroll
        for (int ks2 = 0; ks2 < 4; ks2++) {
            unsigned aP[4];
            aP[0] = __float_as_uint(S.Ps[w][g][ks2 * 8 + t]);
            aP[1] = __float_as_uint(S.Ps[w][g + 8][ks2 * 8 + t]);
            aP[2] = __float_as_uint(S.Ps[w][g][ks2 * 8 + t + 4]);
            aP[3] = __float_as_uint(S.Ps[w][g + 8][ks2 * 8 + t + 4]);
#pragma unroll
            for (int nf = 0; nf < 16; nf++) {
                unsigned bV[2];
                bV[0] = __float_as_uint(S.Vs[ks2 * 8 + t][nf * 8 + g]);
                bV[1] = __float_as_uint(S.Vs[ks2 * 8 + t + 4][nf * 8 + g]);
                mma8(O[nf], aP, bV);
            }
        }
    }

    // epilogue: normalize and store
    float inv0 = 1.f / l0, inv1 = 1.f / l1;
#pragma unroll
    for (int nf = 0; nf < 16; nf++) {
        int cN = nf * 8 + 2 * t;
        *(float2*)(Yb + (size_t)(w * 16 + g) * 2048 + cN) =
            make_float2(O[nf][0] * inv0, O[nf][1] * inv0);
        *(float2*)(Yb + (size_t)(w * 16 + g + 8) * 2048 + cN) =
            make_float2(O[nf][2] * inv1, O[nf][3] * inv1);
    }
}

// ---------------------------------------------------------------------------
// Launch
// ---------------------------------------------------------------------------
extern "C" void kernel_launch(void* const* d_in, const int* in_sizes, int n_in,
                              void* d_out, int out_size) {
    (void)in_sizes; (void)n_in; (void)out_size;
    const float* x  = (const float*)d_in[0];
    const float* Wq = (const float*)d_in[1];
    const float* Wk = (const float*)d_in[2];
    const float* Wv = (const float*)d_in[3];
    const float* Wo = (const float*)d_in[4];
    float* out = (float*)d_out;

    float *Qp, *Kp, *Vp, *AYp;
    cudaGetSymbolAddress((void**)&Qp, g_Q);
    cudaGetSymbolAddress((void**)&Kp, g_K);
    cudaGetSymbolAddress((void**)&Vp, g_V);
    cudaGetSymbolAddress((void**)&AYp, g_AY);

    // Stage 1: QKV projections (M=8192, K=2048)
    gemm_tf32<2048, 2048><<<dim3(16, 64), 256>>>(x, Wq, Qp);
    gemm_tf32<512, 2048><<<dim3(4, 64), 256>>>(x, Wk, Kp);
    gemm_tf32<512, 2048><<<dim3(4, 64), 256>>>(x, Wv, Vp);

    // Stage 2: causal GQA flash attention
    cudaFuncSetAttribute(attn_flash, cudaFuncAttributeMaxDynamicSharedMemorySize,
                         (int)sizeof(AttnSmem));
    attn_flash<<<dim3(32, 16, 4), 128, sizeof(AttnSmem)>>>(Qp, Kp, Vp, AYp);

    // Stage 3: output projection
    gemm_tf32<2048, 2048><<<dim3(16, 64), 256>>>(AYp, Wo, out);
}